// round 2
// baseline (speedup 1.0000x reference)
#include <cuda_runtime.h>

#define SEQ   512
#define BATCH 4096
#define HID   30
#define HP    32
#define ROWPAD 6   // ull entries per k-row (4 used, padded to soften STS bank conflicts)

typedef unsigned long long ull;

__device__ __forceinline__ ull pk2(float a, float b) {
    ull r; asm("mov.b64 %0,{%1,%2};" : "=l"(r) : "f"(a), "f"(b)); return r;
}
__device__ __forceinline__ void unpk2(ull v, float& a, float& b) {
    asm("mov.b64 {%0,%1},%2;" : "=f"(a), "=f"(b) : "l"(v));
}
// Packed dual-fp32 FMA (Blackwell FFMA2) — 2x FFMA throughput per issue slot.
__device__ __forceinline__ ull ffma2(ull a, ull b, ull c) {
    ull d; asm("fma.rn.f32x2 %0,%1,%2,%3;" : "=l"(d) : "l"(a), "l"(b), "l"(c)); return d;
}

// tanh(x) = 1 - 2/(exp2(2x*log2e)+1); ex2/rcp approx are ~ulp-accurate -> error ~1e-7 abs.
__device__ __forceinline__ float tanhfast(float x) {
    float e, r;
    asm("ex2.approx.f32 %0, %1;" : "=f"(e) : "f"(x * 2.8853900817779268f));
    asm("rcp.approx.f32 %0, %1;" : "=f"(r) : "f"(e + 1.0f));
    return fmaf(-2.0f, r, 1.0f);
}

__global__ void __launch_bounds__(32)
rnn_kernel(const float* __restrict__ X,     const float* __restrict__ W_ih,
           const float* __restrict__ W_hh,  const float* __restrict__ b_ih,
           const float* __restrict__ b_hh,  const float* __restrict__ W_out,
           const float* __restrict__ b_out, float* __restrict__ Y)
{
    // h double buffer, stored DUPLICATED: hbuf[buf][k][b] = (h[k][b], h[k][b])
    __shared__ __align__(16) ull hbuf[2][HP][ROWPAD];

    const int lane = threadIdx.x;
    const int jp = lane & 15;        // hidden-unit pair index
    const int bp = lane >> 4;        // batch-pair index within warp (0..1)
    const int j0 = 2 * jp, j1 = j0 + 1;
    const int bbase = blockIdx.x * 4 + bp * 2;   // first of this thread's 2 batches

    // ---- load weights into registers (packed over (j0, j1)) ----
    ull w2[HID];
#pragma unroll
    for (int k = 0; k < HID; k++) {
        float a = (j0 < HID) ? W_hh[j0 * HID + k] : 0.0f;
        float b = (j1 < HID) ? W_hh[j1 * HID + k] : 0.0f;
        w2[k] = pk2(a, b);
    }
    const float wihA = (j0 < HID) ? W_ih[j0] : 0.0f;
    const float wihB = (j1 < HID) ? W_ih[j1] : 0.0f;
    const ull   wih2 = pk2(wihA, wihB);
    const float biA  = (j0 < HID) ? (b_ih[j0] + b_hh[j0]) : 0.0f;
    const float biB  = (j1 < HID) ? (b_ih[j1] + b_hh[j1]) : 0.0f;
    const ull   bias2 = pk2(biA, biB);
    const float wo0 = (j0 < HID) ? W_out[j0] : 0.0f;
    const float wo1 = (j1 < HID) ? W_out[j1] : 0.0f;
    const float bo  = b_out[0];

    // ---- h0 = 0 ----
    hbuf[0][j0][2 * bp]     = 0ull;
    hbuf[0][j0][2 * bp + 1] = 0ull;
    hbuf[0][j1][2 * bp]     = 0ull;
    hbuf[0][j1][2 * bp + 1] = 0ull;
    __syncwarp();

    const float* Xp = X + bbase;
    float*       Yp = Y + bbase;

    // y-reduction is pipelined one step late so SHFL latency hides under FFMA2s
    float pp0 = 0.0f, pp1 = 0.0f;

    for (int s = 0; s < SEQ; s++) {
        const int cur = s & 1, nxt = cur ^ 1;

        // previous step's y: warp-reduce over the 16 jp lanes, then store
        if (s > 0) {
            float r0 = pp0, r1 = pp1;
#pragma unroll
            for (int m = 1; m < 16; m <<= 1) {
                r0 += __shfl_xor_sync(0xffffffffu, r0, m);
                r1 += __shfl_xor_sync(0xffffffffu, r1, m);
            }
            if (jp == 0) {
                float2 yv = make_float2(r0 + bo, r1 + bo);
                *(float2*)(Yp + (s - 1) * BATCH) = yv;
            }
        }

        // x for this step (consumed only after the k-loop -> latency hidden)
        const float2 x2 = *(const float2*)(Xp + s * BATCH);

        // ---- matvec: acc[j0,j1] += sum_k W[j][k] * h[k] for both batches ----
        ull acc0 = bias2, acc1 = bias2;
#pragma unroll
        for (int k = 0; k < HID; k++) {
            ulonglong2 hv = *((const ulonglong2*)&hbuf[cur][k][2 * bp]);
            acc0 = ffma2(w2[k], hv.x, acc0);   // batch b0
            acc1 = ffma2(w2[k], hv.y, acc1);   // batch b1
        }
        acc0 = ffma2(wih2, pk2(x2.x, x2.x), acc0);
        acc1 = ffma2(wih2, pk2(x2.y, x2.y), acc1);

        // ---- tanh ----
        float a00, a10, a01, a11;
        unpk2(acc0, a00, a10);   // (j0,b0), (j1,b0)
        unpk2(acc1, a01, a11);   // (j0,b1), (j1,b1)
        const float h00 = tanhfast(a00);
        const float h10 = tanhfast(a10);
        const float h01 = tanhfast(a01);
        const float h11 = tanhfast(a11);

        // ---- publish h_{s+1} (duplicated) ----
        hbuf[nxt][j0][2 * bp]     = pk2(h00, h00);
        hbuf[nxt][j0][2 * bp + 1] = pk2(h01, h01);
        hbuf[nxt][j1][2 * bp]     = pk2(h10, h10);
        hbuf[nxt][j1][2 * bp + 1] = pk2(h11, h11);

        // ---- y partials for this step (reduced next iteration) ----
        pp0 = fmaf(h00, wo0, h10 * wo1);
        pp1 = fmaf(h01, wo0, h11 * wo1);

        __syncwarp();
    }

    // final step's y
    {
        float r0 = pp0, r1 = pp1;
#pragma unroll
        for (int m = 1; m < 16; m <<= 1) {
            r0 += __shfl_xor_sync(0xffffffffu, r0, m);
            r1 += __shfl_xor_sync(0xffffffffu, r1, m);
        }
        if (jp == 0) {
            float2 yv = make_float2(r0 + bo, r1 + bo);
            *(float2*)(Yp + (SEQ - 1) * BATCH) = yv;
        }
    }
}

extern "C" void kernel_launch(void* const* d_in, const int* in_sizes, int n_in,
                              void* d_out, int out_size)
{
    (void)in_sizes; (void)n_in; (void)out_size;
    rnn_kernel<<<BATCH / 4, 32>>>(
        (const float*)d_in[0],  // X
        (const float*)d_in[1],  // W_ih
        (const float*)d_in[2],  // W_hh
        (const float*)d_in[3],  // b_ih
        (const float*)d_in[4],  // b_hh
        (const float*)d_in[5],  // W_out
        (const float*)d_in[6],  // b_out
        (float*)d_out);
}

// round 3
// speedup vs baseline: 1.1406x; 1.1406x over previous
#include <cuda_runtime.h>

#define SEQ   512
#define BATCH 4096
#define HID   30
#define HROW  34   // ull entries per (buf,batch) row: 32 used + 2 pad (272B, breaks bank alias)

typedef unsigned long long ull;

__device__ __forceinline__ ull pk2(float a, float b) {
    ull r; asm("mov.b64 %0,{%1,%2};" : "=l"(r) : "f"(a), "f"(b)); return r;
}
__device__ __forceinline__ void unpk2(ull v, float& a, float& b) {
    asm("mov.b64 {%0,%1},%2;" : "=f"(a), "=f"(b) : "l"(v));
}
// Packed dual-fp32 FMA / ADD (Blackwell f32x2) — 2 lanes of fp32 per issue.
__device__ __forceinline__ ull ffma2(ull a, ull b, ull c) {
    ull d; asm("fma.rn.f32x2 %0,%1,%2,%3;" : "=l"(d) : "l"(a), "l"(b), "l"(c)); return d;
}
__device__ __forceinline__ ull add2(ull a, ull b) {
    ull d; asm("add.rn.f32x2 %0,%1,%2;" : "=l"(d) : "l"(a), "l"(b)); return d;
}

// tanh(x) = 1 - 2/(exp2(2x*log2e)+1); ex2/rcp approx -> ~1e-7 abs error.
__device__ __forceinline__ float tanhfast(float x) {
    float e, r;
    asm("ex2.approx.f32 %0, %1;" : "=f"(e) : "f"(x * 2.8853900817779268f));
    asm("rcp.approx.f32 %0, %1;" : "=f"(r) : "f"(e + 1.0f));
    return fmaf(-2.0f, r, 1.0f);
}

__global__ void __launch_bounds__(32)
rnn_kernel(const float* __restrict__ X,     const float* __restrict__ W_ih,
           const float* __restrict__ W_hh,  const float* __restrict__ b_ih,
           const float* __restrict__ b_hh,  const float* __restrict__ W_out,
           const float* __restrict__ b_out, float* __restrict__ Y)
{
    // h double buffer, DUPLICATED per entry: hbuf[buf][b][k] = (h[k], h[k])
    __shared__ __align__(16) ull hbuf[2][2][HROW];

    const int lane = threadIdx.x;
    const int jp   = lane & 15;            // hidden-unit pair index
    const int b    = lane >> 4;            // which of this warp's 2 batches
    const int j0   = 2 * jp, j1 = j0 + 1;
    const int batch = blockIdx.x * 2 + b;

    // ---- weights in registers, packed over (j0, j1) ----
    ull w2[HID];
#pragma unroll
    for (int k = 0; k < HID; k++) {
        float a = (j0 < HID) ? W_hh[j0 * HID + k] : 0.0f;
        float c = (j1 < HID) ? W_hh[j1 * HID + k] : 0.0f;
        w2[k] = pk2(a, c);
    }
    const ull wih2 = pk2((j0 < HID) ? W_ih[j0] : 0.0f,
                         (j1 < HID) ? W_ih[j1] : 0.0f);
    const ull bias2 = pk2((j0 < HID) ? (b_ih[j0] + b_hh[j0]) : 0.0f,
                          (j1 < HID) ? (b_ih[j1] + b_hh[j1]) : 0.0f);
    const float wo0 = (j0 < HID) ? W_out[j0] : 0.0f;
    const float wo1 = (j1 < HID) ? W_out[j1] : 0.0f;
    const float bo  = b_out[0];

    // ---- h0 = 0 (each thread zeroes its two rows in buffer 0) ----
    hbuf[0][b][j0] = 0ull;
    hbuf[0][b][j1] = 0ull;
    __syncwarp();

    const float* Xb = X + batch;
    float*       Yb = Y + batch;

    float pp = 0.0f;                 // y partial, reduced one step late
    float xcur = Xb[0];              // x prefetch pipeline

    for (int s = 0; s < SEQ; s++) {
        const ull* hc = &hbuf[s & 1][b][0];
        ull*       hn = &hbuf[(s & 1) ^ 1][b][0];

        // ---- previous step's y: butterfly-reduce within each 16-lane half ----
        if (s > 0) {
            float r = pp;
#pragma unroll
            for (int m = 1; m < 16; m <<= 1)
                r += __shfl_xor_sync(0xffffffffu, r, m);
            if (jp == 0) Yb[(s - 1) * BATCH] = r + bo;
        }

        // ---- start next x load (DRAM latency hidden under this step) ----
        const float xc = xcur;
        if (s + 1 < SEQ) xcur = Xb[(s + 1) * BATCH];

        // ---- matvec with 4 split accumulator chains ----
        ull a0 = bias2, a1 = 0ull, a2 = 0ull, a3 = 0ull;
#pragma unroll
        for (int i = 0; i < 15; i++) {
            ulonglong2 hv = *(const ulonglong2*)&hc[2 * i];   // (dup h[2i], dup h[2i+1])
            if (i & 1) {
                a2 = ffma2(w2[2 * i],     hv.x, a2);
                a3 = ffma2(w2[2 * i + 1], hv.y, a3);
            } else {
                a0 = ffma2(w2[2 * i],     hv.x, a0);
                a1 = ffma2(w2[2 * i + 1], hv.y, a1);
            }
        }
        a0 = ffma2(wih2, pk2(xc, xc), a0);
        const ull acc = add2(add2(a0, a2), add2(a1, a3));

        // ---- tanh ----
        float v0, v1;
        unpk2(acc, v0, v1);
        const float h0 = tanhfast(v0);
        const float h1 = tanhfast(v1);

        // ---- publish h_{s+1}: one STS.128, duplicated layout ----
        ulonglong2 st;
        st.x = pk2(h0, h0);
        st.y = pk2(h1, h1);
        *(ulonglong2*)&hn[j0] = st;

        // ---- this step's y partial (reduced next iteration) ----
        pp = fmaf(h0, wo0, h1 * wo1);

        __syncwarp();
    }

    // final step's y
    {
        float r = pp;
#pragma unroll
        for (int m = 1; m < 16; m <<= 1)
            r += __shfl_xor_sync(0xffffffffu, r, m);
        if (jp == 0) Yb[(SEQ - 1) * BATCH] = r + bo;
    }
}

extern "C" void kernel_launch(void* const* d_in, const int* in_sizes, int n_in,
                              void* d_out, int out_size)
{
    (void)in_sizes; (void)n_in; (void)out_size;
    rnn_kernel<<<BATCH / 2, 32>>>(
        (const float*)d_in[0],  // X
        (const float*)d_in[1],  // W_ih
        (const float*)d_in[2],  // W_hh
        (const float*)d_in[3],  // b_ih
        (const float*)d_in[4],  // b_hh
        (const float*)d_in[5],  // W_out
        (const float*)d_in[6],  // b_out
        (float*)d_out);
}